// round 3
// baseline (speedup 1.0000x reference)
#include <cuda_runtime.h>
#include <math.h>

#define TPB 256
#define RT  8             // rows per CTA
#define RP  4             // row pairs (RT/2)

#define D_IN   480
#define NM0    128
#define NM1    64
#define NM2    32
#define NH0    512
#define NH1    256
#define NH2    128
#define W0COLS 896        // H0 + G

#define EPSF    1e-8f
#define INV_S0  0.08838834764831845f   // 1/sqrt(128)
#define INV_S1  0.125f                 // 1/sqrt(64)
#define INV_S2  0.17677669529663687f   // 1/sqrt(32)
#define INV_T0  0.04419417382415922f   // 1/sqrt(512)
#define INV_T1  0.0625f                // 1/sqrt(256)
#define INV_T2  0.08838834764831845f   // 1/sqrt(128)

typedef unsigned long long u64t;

// ---- packed f32x2 helpers (Blackwell FFMA2 path; rt beats scalar FFMA 2x) ----
__device__ __forceinline__ u64t pk2(float v) {
    u64t r; asm("mov.b64 %0, {%1, %1};" : "=l"(r) : "f"(v)); return r;
}
__device__ __forceinline__ void fm2(u64t& d, u64t a, u64t b) {
    asm("fma.rn.f32x2 %0, %1, %2, %0;" : "+l"(d) : "l"(a), "l"(b));
}
__device__ __forceinline__ u64t ml2(u64t a, u64t b) {
    u64t r; asm("mul.rn.f32x2 %0, %1, %2;" : "=l"(r) : "l"(a), "l"(b)); return r;
}
__device__ __forceinline__ float2 up2(u64t v) {
    float2 f; asm("mov.b64 {%0, %1}, %2;" : "=f"(f.x), "=f"(f.y) : "l"(v)); return f;
}

// All [col][row] arrays use RT=8 row-minor: one col = 4 contiguous f32x2 pairs.
struct Smem {
    float y0[NM0 * RT];           //  4 KB
    float y1[3 * NM1 * RT];       //  6 KB
    float y2[5 * NM2 * RT];       //  5 KB
    float s [NH0 * RT];           // 16 KB  silu(h0[:512]) * (1/T0)
    float g [(NH1 + NH2) * RT];   // 12 KB  sigmoid(h0[512:])
    float z1[3 * NH1 * RT];       // 24 KB
    float z2[5 * NH2 * RT];       // 20 KB
    float o0[RT * NM0];           //  4 KB  r-major
    float o1[RT * 3 * NM1];       //  6 KB  r-major
    float o2[RT * 5 * NM2];       //  5 KB  r-major
    float scratch[RT * NM0];      //  4 KB
};                                // ~106 KB -> 2 CTAs/SM

__global__ __launch_bounds__(TPB, 2)
void ffn_kernel(const float* __restrict__ x,
                const float* __restrict__ nw0, const float* __restrict__ nb0,
                const float* __restrict__ nw1, const float* __restrict__ nw2,
                const float* __restrict__ W0,  const float* __restrict__ b0,
                const float* __restrict__ W1,  const float* __restrict__ W2,
                const float* __restrict__ V0,  const float* __restrict__ c0,
                const float* __restrict__ V1,  const float* __restrict__ V2,
                const float* __restrict__ alpha,
                float* __restrict__ out)
{
    extern __shared__ float smem_raw[];
    Smem& sm = *reinterpret_cast<Smem*>(smem_raw);
    const int tid  = threadIdx.x;
    const int row0 = blockIdx.x * RT;

    // ================= Stage 1: norms (1 warp per row) =================
    {
        const int warp = tid >> 5, lane = tid & 31;
        const int r = warp;
        const float* xr = x + (size_t)(row0 + r) * D_IN;
        float vals[15];
        float sum0 = 0.f, sq0 = 0.f, sq12 = 0.f;
        #pragma unroll
        for (int k = 0; k < 15; ++k) {
            const int c = lane + 32 * k;
            const float v = xr[c];
            vals[k] = v;
            if (k < 4)       { sum0 += v; sq0 += v * v; }
            else if (k < 10) { sq12 += v * v * (0.5f / 192.0f); }
            else             { sq12 += v * v * (0.5f / 160.0f); }
        }
        #pragma unroll
        for (int o = 16; o > 0; o >>= 1) {
            sum0 += __shfl_xor_sync(0xffffffffu, sum0, o);
            sq0  += __shfl_xor_sync(0xffffffffu, sq0,  o);
            sq12 += __shfl_xor_sync(0xffffffffu, sq12, o);
        }
        const float mu    = sum0 * (1.0f / 128.0f);
        const float var   = sq0 * (1.0f / 128.0f) - mu * mu;
        const float is0   = rsqrtf(var + EPSF);
        const float inv12 = rsqrtf(sq12 + EPSF);
        #pragma unroll
        for (int k = 0; k < 15; ++k) {
            const int c = lane + 32 * k;
            const float v = vals[k];
            if (k < 4) {
                sm.y0[c * RT + r] = ((v - mu) * is0 * nw0[c] + nb0[c]) * INV_S0;
            } else if (k < 10) {
                const int cc = c - 128; const int u = cc / 3; const int m = cc - 3 * u;
                sm.y1[(m * NM1 + u) * RT + r] = v * inv12 * nw1[u] * INV_S1;
            } else {
                const int cc = c - 320; const int u = cc / 5; const int m = cc - 5 * u;
                sm.y2[(m * NM2 + u) * RT + r] = v * inv12 * nw2[u] * INV_S2;
            }
        }
    }
    __syncthreads();

    // ================= Stage 2a: H0 = Y0 @ W0 (+b0), activations ===========
    if (tid < 224) {
        const int j0 = tid * 4;
        u64t acc[4][RP];
        #pragma unroll
        for (int c = 0; c < 4; ++c)
            #pragma unroll
            for (int p = 0; p < RP; ++p) acc[c][p] = 0ull;

        float4 w = *(const float4*)(W0 + j0);
        for (int u = 0; u < NM0; ++u) {
            const int un = (u < NM0 - 1) ? u + 1 : u;
            const float4 wn = *(const float4*)(W0 + un * W0COLS + j0);
            const ulonglong2* yp = (const ulonglong2*)(sm.y0 + u * RT);
            const ulonglong2 ya = yp[0], yb = yp[1];
            u64t yv[RP] = {ya.x, ya.y, yb.x, yb.y};
            u64t wp[4]  = {pk2(w.x), pk2(w.y), pk2(w.z), pk2(w.w)};
            #pragma unroll
            for (int c = 0; c < 4; ++c)
                #pragma unroll
                for (int p = 0; p < RP; ++p) fm2(acc[c][p], yv[p], wp[c]);
            w = wn;
        }
        #pragma unroll
        for (int c = 0; c < 4; ++c) {
            const int col = j0 + c;
            const float bb = b0[col];
            float h[RT];
            #pragma unroll
            for (int p = 0; p < RP; ++p) {
                const float2 f = up2(acc[c][p]);
                h[2*p] = f.x + bb; h[2*p+1] = f.y + bb;
            }
            if (col < NH0) {
                #pragma unroll
                for (int q = 0; q < 2; ++q) {
                    float4 o;
                    o.x = h[4*q+0] * __fdividef(1.f, 1.f + __expf(-h[4*q+0])) * INV_T0;
                    o.y = h[4*q+1] * __fdividef(1.f, 1.f + __expf(-h[4*q+1])) * INV_T0;
                    o.z = h[4*q+2] * __fdividef(1.f, 1.f + __expf(-h[4*q+2])) * INV_T0;
                    o.w = h[4*q+3] * __fdividef(1.f, 1.f + __expf(-h[4*q+3])) * INV_T0;
                    ((float4*)(sm.s + col * RT))[q] = o;
                }
            } else {
                #pragma unroll
                for (int q = 0; q < 2; ++q) {
                    float4 o;
                    o.x = __fdividef(1.f, 1.f + __expf(-h[4*q+0]));
                    o.y = __fdividef(1.f, 1.f + __expf(-h[4*q+1]));
                    o.z = __fdividef(1.f, 1.f + __expf(-h[4*q+2]));
                    o.w = __fdividef(1.f, 1.f + __expf(-h[4*q+3]));
                    ((float4*)(sm.g + (col - NH0) * RT))[q] = o;
                }
            }
        }
    }
    __syncthreads();

    // ================= Stage 2b: h1 -> z1 (3 heads) ========================
    if (tid < 192) {
        const int m  = tid >> 6;
        const int j0 = (tid & 63) * 4;
        u64t acc[4][RP];
        #pragma unroll
        for (int c = 0; c < 4; ++c)
            #pragma unroll
            for (int p = 0; p < RP; ++p) acc[c][p] = 0ull;

        const float* yb0 = sm.y1 + (m * NM1) * RT;
        float4 w = *(const float4*)(W1 + j0);
        for (int u = 0; u < NM1; ++u) {
            const int un = (u < NM1 - 1) ? u + 1 : u;
            const float4 wn = *(const float4*)(W1 + un * NH1 + j0);
            const ulonglong2* yp = (const ulonglong2*)(yb0 + u * RT);
            const ulonglong2 ya = yp[0], yq = yp[1];
            u64t yv[RP] = {ya.x, ya.y, yq.x, yq.y};
            u64t wp[4]  = {pk2(w.x), pk2(w.y), pk2(w.z), pk2(w.w)};
            #pragma unroll
            for (int c = 0; c < 4; ++c)
                #pragma unroll
                for (int p = 0; p < RP; ++p) fm2(acc[c][p], yv[p], wp[c]);
            w = wn;
        }
        const u64t sc = pk2(INV_T1);
        #pragma unroll
        for (int c = 0; c < 4; ++c) {
            const int col = j0 + c;
            const ulonglong2* gp = (const ulonglong2*)(sm.g + col * RT);
            const ulonglong2 ga = gp[0], gb = gp[1];
            u64t gv[RP] = {ga.x, ga.y, gb.x, gb.y};
            ulonglong2* zp = (ulonglong2*)(sm.z1 + (m * NH1 + col) * RT);
            ulonglong2 z0, z1v;
            z0.x  = ml2(ml2(acc[c][0], gv[0]), sc);
            z0.y  = ml2(ml2(acc[c][1], gv[1]), sc);
            z1v.x = ml2(ml2(acc[c][2], gv[2]), sc);
            z1v.y = ml2(ml2(acc[c][3], gv[3]), sc);
            zp[0] = z0; zp[1] = z1v;
        }
    }

    // ================= Stage 2c: h2 -> z2 (5 heads) ========================
    if (tid >= 96) {
        const int t  = tid - 96;
        const int m  = t >> 5;
        const int j0 = (t & 31) * 4;
        u64t acc[4][RP];
        #pragma unroll
        for (int c = 0; c < 4; ++c)
            #pragma unroll
            for (int p = 0; p < RP; ++p) acc[c][p] = 0ull;

        const float* yb0 = sm.y2 + (m * NM2) * RT;
        float4 w = *(const float4*)(W2 + j0);
        for (int u = 0; u < NM2; ++u) {
            const int un = (u < NM2 - 1) ? u + 1 : u;
            const float4 wn = *(const float4*)(W2 + un * NH2 + j0);
            const ulonglong2* yp = (const ulonglong2*)(yb0 + u * RT);
            const ulonglong2 ya = yp[0], yq = yp[1];
            u64t yv[RP] = {ya.x, ya.y, yq.x, yq.y};
            u64t wp[4]  = {pk2(w.x), pk2(w.y), pk2(w.z), pk2(w.w)};
            #pragma unroll
            for (int c = 0; c < 4; ++c)
                #pragma unroll
                for (int p = 0; p < RP; ++p) fm2(acc[c][p], yv[p], wp[c]);
            w = wn;
        }
        const u64t sc = pk2(INV_T2);
        #pragma unroll
        for (int c = 0; c < 4; ++c) {
            const int col = j0 + c;
            const ulonglong2* gp = (const ulonglong2*)(sm.g + (NH1 + col) * RT);
            const ulonglong2 ga = gp[0], gb = gp[1];
            u64t gv[RP] = {ga.x, ga.y, gb.x, gb.y};
            ulonglong2* zp = (ulonglong2*)(sm.z2 + (m * NH2 + col) * RT);
            ulonglong2 z0, z1v;
            z0.x  = ml2(ml2(acc[c][0], gv[0]), sc);
            z0.y  = ml2(ml2(acc[c][1], gv[1]), sc);
            z1v.x = ml2(ml2(acc[c][2], gv[2]), sc);
            z1v.y = ml2(ml2(acc[c][3], gv[3]), sc);
            zp[0] = z0; zp[1] = z1v;
        }
    }
    __syncthreads();

    // ================= Stage 4a: o0 = s @ V0 (+c0), K-split by 2 ===========
    u64t acc0[RP];
    {
        const int j  = tid & 127;
        const int kh = tid >> 7;
        #pragma unroll
        for (int p = 0; p < RP; ++p) acc0[p] = 0ull;
        const int ub = kh * 256;
        for (int uu = 0; uu < 256; uu += 4) {
            const float w0_ = V0[(ub + uu + 0) * NM0 + j];
            const float w1_ = V0[(ub + uu + 1) * NM0 + j];
            const float w2_ = V0[(ub + uu + 2) * NM0 + j];
            const float w3_ = V0[(ub + uu + 3) * NM0 + j];
            #pragma unroll
            for (int q = 0; q < 4; ++q) {
                const float wsc = (q == 0) ? w0_ : (q == 1) ? w1_ : (q == 2) ? w2_ : w3_;
                const u64t wq = pk2(wsc);
                const ulonglong2* sp = (const ulonglong2*)(sm.s + (ub + uu + q) * RT);
                const ulonglong2 sa = sp[0], sb = sp[1];
                fm2(acc0[0], sa.x, wq); fm2(acc0[1], sa.y, wq);
                fm2(acc0[2], sb.x, wq); fm2(acc0[3], sb.y, wq);
            }
        }
        if (kh) {
            #pragma unroll
            for (int p = 0; p < RP; ++p) {
                const float2 f = up2(acc0[p]);
                sm.scratch[(2*p)   * NM0 + j] = f.x;
                sm.scratch[(2*p+1) * NM0 + j] = f.y;
            }
        }
    }
    __syncthreads();
    if (tid < 128) {
        const float cc = c0[tid];
        #pragma unroll
        for (int p = 0; p < RP; ++p) {
            const float2 f = up2(acc0[p]);
            sm.o0[(2*p)   * NM0 + tid] = f.x + sm.scratch[(2*p)   * NM0 + tid] + cc;
            sm.o0[(2*p+1) * NM0 + tid] = f.y + sm.scratch[(2*p+1) * NM0 + tid] + cc;
        }
    }

    // ================= Stage 4b: o1 = z1 @ V1 ==============================
    if (tid < 192) {
        const int m = tid >> 6;
        const int j = tid & 63;
        u64t acc[RP];
        #pragma unroll
        for (int p = 0; p < RP; ++p) acc[p] = 0ull;
        const float* zb = sm.z1 + (m * NH1) * RT;
        for (int u = 0; u < NH1; u += 4) {
            const float w0_ = V1[(u + 0) * NM1 + j];
            const float w1_ = V1[(u + 1) * NM1 + j];
            const float w2_ = V1[(u + 2) * NM1 + j];
            const float w3_ = V1[(u + 3) * NM1 + j];
            #pragma unroll
            for (int q = 0; q < 4; ++q) {
                const float wsc = (q == 0) ? w0_ : (q == 1) ? w1_ : (q == 2) ? w2_ : w3_;
                const u64t wq = pk2(wsc);
                const ulonglong2* sp = (const ulonglong2*)(zb + (u + q) * RT);
                const ulonglong2 sa = sp[0], sb = sp[1];
                fm2(acc[0], sa.x, wq); fm2(acc[1], sa.y, wq);
                fm2(acc[2], sb.x, wq); fm2(acc[3], sb.y, wq);
            }
        }
        #pragma unroll
        for (int p = 0; p < RP; ++p) {
            const float2 f = up2(acc[p]);
            sm.o1[(2*p)   * (3 * NM1) + m * NM1 + j] = f.x;
            sm.o1[(2*p+1) * (3 * NM1) + m * NM1 + j] = f.y;
        }
    }

    // ================= Stage 4c: o2 = z2 @ V2 ==============================
    if (tid >= 96) {
        const int t = tid - 96;
        const int m = t >> 5;
        const int j = t & 31;
        u64t acc[RP];
        #pragma unroll
        for (int p = 0; p < RP; ++p) acc[p] = 0ull;
        const float* zb = sm.z2 + (m * NH2) * RT;
        for (int u = 0; u < NH2; u += 4) {
            const float w0_ = V2[(u + 0) * NM2 + j];
            const float w1_ = V2[(u + 1) * NM2 + j];
            const float w2_ = V2[(u + 2) * NM2 + j];
            const float w3_ = V2[(u + 3) * NM2 + j];
            #pragma unroll
            for (int q = 0; q < 4; ++q) {
                const float wsc = (q == 0) ? w0_ : (q == 1) ? w1_ : (q == 2) ? w2_ : w3_;
                const u64t wq = pk2(wsc);
                const ulonglong2* sp = (const ulonglong2*)(zb + (u + q) * RT);
                const ulonglong2 sa = sp[0], sb = sp[1];
                fm2(acc[0], sa.x, wq); fm2(acc[1], sa.y, wq);
                fm2(acc[2], sb.x, wq); fm2(acc[3], sb.y, wq);
            }
        }
        #pragma unroll
        for (int p = 0; p < RP; ++p) {
            const float2 f = up2(acc[p]);
            sm.o2[(2*p)   * (5 * NM2) + m * NM2 + j] = f.x;
            sm.o2[(2*p+1) * (5 * NM2) + m * NM2 + j] = f.y;
        }
    }
    __syncthreads();

    // ================= Stage 5: out = x + tanh(alpha) * dx =================
    {
        const float t = tanhf(alpha[0]);
        #pragma unroll
        for (int i = tid; i < RT * D_IN; i += TPB) {
            const int r = i / D_IN;
            const int c = i - r * D_IN;
            float dx;
            if (c < 128) {
                dx = sm.o0[r * NM0 + c];
            } else if (c < 320) {
                const int cc = c - 128; const int u = cc / 3; const int m = cc - 3 * u;
                dx = sm.o1[r * (3 * NM1) + m * NM1 + u];
            } else {
                const int cc = c - 320; const int u = cc / 5; const int m = cc - 5 * u;
                dx = sm.o2[r * (5 * NM2) + m * NM2 + u];
            }
            const size_t idx = (size_t)(row0 + r) * D_IN + c;
            out[idx] = x[idx] + t * dx;
        }
    }
}

extern "C" void kernel_launch(void* const* d_in, const int* in_sizes, int n_in,
                              void* d_out, int out_size) {
    const float* x     = (const float*)d_in[0];
    const float* nw0   = (const float*)d_in[1];
    const float* nb0   = (const float*)d_in[2];
    const float* nw1   = (const float*)d_in[3];
    const float* nw2   = (const float*)d_in[4];
    const float* W0    = (const float*)d_in[5];
    const float* b0    = (const float*)d_in[6];
    const float* W1    = (const float*)d_in[7];
    const float* W2    = (const float*)d_in[8];
    const float* V0    = (const float*)d_in[9];
    const float* c0    = (const float*)d_in[10];
    const float* V1    = (const float*)d_in[11];
    const float* V2    = (const float*)d_in[12];
    const float* alpha = (const float*)d_in[13];
    float* out = (float*)d_out;

    const int n = in_sizes[0] / D_IN;
    const int grid = n / RT;

    cudaFuncSetAttribute(ffn_kernel, cudaFuncAttributeMaxDynamicSharedMemorySize,
                         (int)sizeof(Smem));
    ffn_kernel<<<grid, TPB, sizeof(Smem)>>>(x, nw0, nb0, nw1, nw2, W0, b0, W1, W2,
                                            V0, c0, V1, V2, alpha, out);
}

// round 6
// speedup vs baseline: 1.8689x; 1.8689x over previous
#include <cuda_runtime.h>
#include <math.h>

#define TPB 512
#define MR  64

#define EPSF    1e-8f
#define INV_S0  0.08838834764831845f
#define INV_S1  0.125f
#define INV_S2  0.17677669529663687f
#define INV_T0  0.04419417382415922f
#define INV_T1  0.0625f
#define INV_T2  0.08838834764831845f

// smem word offsets
#define INVA 0
#define Y0F  64
#define AFB  (Y0F + 8192)
#define STGB (AFB + 4096)
#define LB0  (STGB + 8192)
#define YMF  (LB0 + 4352)
#define LB1  (YMF + 12288)
#define SMW  (LB1 + 4352)           // 41536 words = 166144 B

// fragment-order weight buffers (tf32 bit patterns)
__device__ __align__(16) float W0F_g[114688];
__device__ __align__(16) float V0F_g[65536];
__device__ __align__(16) float W1F_g[16384];
__device__ __align__(16) float V1F_g[16384];
__device__ __align__(16) float W2F_g[4096];
__device__ __align__(16) float V2F_g[4096];

__device__ __forceinline__ unsigned cvt_tf32(float v) {
    unsigned r; asm("cvt.rna.tf32.f32 %0, %1;" : "=r"(r) : "f"(v)); return r;
}
__device__ __forceinline__ void mma8(float* d, const uint4 a, const uint2 b) {
    asm volatile(
        "mma.sync.aligned.m16n8k8.row.col.f32.tf32.tf32.f32 "
        "{%0,%1,%2,%3}, {%4,%5,%6,%7}, {%8,%9}, {%0,%1,%2,%3};"
        : "+f"(d[0]), "+f"(d[1]), "+f"(d[2]), "+f"(d[3])
        : "r"(a.x), "r"(a.y), "r"(a.z), "r"(a.w), "r"(b.x), "r"(b.y));
}
// dest word -> (row, k) of the A-fragment layout
__device__ __forceinline__ void frag_src(int i, int& r, int& k) {
    const int j = i & 3, lane = (i >> 2) & 31, blk = i >> 7;
    const int ms = blk & 3, kb = blk >> 2;
    r = 16 * ms + (lane >> 2) + 8 * (j & 1);
    k = 8 * kb + (lane & 3) + 4 * (j >> 1);
}
__device__ __forceinline__ void copy4(float* SM, int dst, const float* src, int nwords) {
    const int n4 = nwords >> 2;
    uint4* d = (uint4*)(SM + dst);
    const uint4* s = (const uint4*)src;
    for (int i = threadIdx.x; i < n4; i += TPB) d[i] = s[i];
}
__device__ __forceinline__ void refrag(float* SM, int dstF, int srcL) {
    for (int i = threadIdx.x; i < 4096; i += TPB) {
        int r, k; frag_src(i, r, k);
        unsigned v = cvt_tf32(SM[srcL + r * 68 + k]);
        SM[dstF + i] = __uint_as_float(v);
    }
}
// N=64 GEMM: warp ns covers cols [16*ns, 16*ns+16)
__device__ __forceinline__ void gemm_n64(const float* SM, int aW, int bW, int KB,
                                         int ms, int ns, int lane, float acc[2][4]) {
    const uint4* A = (const uint4*)(SM + aW);
    const uint2* B = (const uint2*)(SM + bW);
    for (int kb = 0; kb < KB; ++kb) {
        const uint4 a  = A[(kb * 4 + ms) * 32 + lane];
        const uint2 b0 = B[(kb * 8 + ns * 2 + 0) * 32 + lane];
        const uint2 b1 = B[(kb * 8 + ns * 2 + 1) * 32 + lane];
        mma8(acc[0], a, b0);
        mma8(acc[1], a, b1);
    }
}
// N=128 GEMM: warp ns covers cols [32*ns, 32*ns+32)
__device__ __forceinline__ void gemm_n128(const float* SM, int aW, int bW, int KB,
                                          int ms, int ns, int lane, float acc[4][4]) {
    const uint4* A = (const uint4*)(SM + aW);
    const uint2* B = (const uint2*)(SM + bW);
    for (int kb = 0; kb < KB; ++kb) {
        const uint4 a = A[(kb * 4 + ms) * 32 + lane];
        #pragma unroll
        for (int t = 0; t < 4; ++t) {
            const uint2 b = B[(kb * 16 + ns * 4 + t) * 32 + lane];
            mma8(acc[t], a, b);
        }
    }
}
// N=32 GEMM: warp ns covers cols [8*ns, 8*ns+8)
__device__ __forceinline__ void gemm_n32(const float* SM, int aW, int bW, int KB,
                                         int ms, int ns, int lane, float acc[4]) {
    const uint4* A = (const uint4*)(SM + aW);
    const uint2* B = (const uint2*)(SM + bW);
    for (int kb = 0; kb < KB; ++kb) {
        const uint4 a = A[(kb * 4 + ms) * 32 + lane];
        const uint2 b = B[(kb * 4 + ns) * 32 + lane];
        mma8(acc, a, b);
    }
}

// ---------------- prep: weights -> tf32 fragment order ----------------
__global__ __launch_bounds__(256)
void prep_kernel(const float* __restrict__ W0, const float* __restrict__ W1,
                 const float* __restrict__ W2, const float* __restrict__ V0,
                 const float* __restrict__ V1, const float* __restrict__ V2) {
    const int st = gridDim.x * blockDim.x, t0 = blockIdx.x * blockDim.x + threadIdx.x;
    for (int i = t0; i < 114688; i += st) {
        const int c = i >> 13, w = i & 8191, blk = w >> 6, wi = w & 63;
        const int kb = blk >> 3, nt = blk & 7, lane = wi >> 1, j = wi & 1;
        const int n = 64 * c + 8 * nt + (lane >> 2), k = 8 * kb + (lane & 3) + 4 * j;
        W0F_g[i] = __uint_as_float(cvt_tf32(W0[k * 896 + n]));
    }
    for (int i = t0; i < 65536; i += st) {
        const int c = i >> 13, w = i & 8191, blk = w >> 6, wi = w & 63;
        const int kb = blk >> 4, nt = blk & 15, lane = wi >> 1, j = wi & 1;
        const int k = 64 * c + 8 * kb + (lane & 3) + 4 * j, n = 8 * nt + (lane >> 2);
        V0F_g[i] = __uint_as_float(cvt_tf32(V0[k * 128 + n]));
    }
    for (int i = t0; i < 16384; i += st) {
        const int c = i >> 12, w = i & 4095, blk = w >> 6, wi = w & 63;
        const int kb = blk >> 3, nt = blk & 7, lane = wi >> 1, j = wi & 1;
        const int n = 64 * c + 8 * nt + (lane >> 2), k = 8 * kb + (lane & 3) + 4 * j;
        W1F_g[i] = __uint_as_float(cvt_tf32(W1[k * 256 + n]));
    }
    for (int i = t0; i < 16384; i += st) {
        const int c = i >> 12, w = i & 4095, blk = w >> 6, wi = w & 63;
        const int kb = blk >> 3, nt = blk & 7, lane = wi >> 1, j = wi & 1;
        const int k = 64 * c + 8 * kb + (lane & 3) + 4 * j, n = 8 * nt + (lane >> 2);
        V1F_g[i] = __uint_as_float(cvt_tf32(V1[k * 64 + n]));
    }
    for (int i = t0; i < 4096; i += st) {
        const int c = i >> 11, w = i & 2047, blk = w >> 6, wi = w & 63;
        const int kb = blk >> 3, nt = blk & 7, lane = wi >> 1, j = wi & 1;
        const int n = 64 * c + 8 * nt + (lane >> 2), k = 8 * kb + (lane & 3) + 4 * j;
        W2F_g[i] = __uint_as_float(cvt_tf32(W2[k * 128 + n]));
    }
    for (int i = t0; i < 4096; i += st) {
        const int c = i >> 11, w = i & 2047, blk = w >> 6, wi = w & 63;
        const int kb = blk >> 2, nt = blk & 3, lane = wi >> 1, j = wi & 1;
        const int k = 64 * c + 8 * kb + (lane & 3) + 4 * j, n = 8 * nt + (lane >> 2);
        V2F_g[i] = __uint_as_float(cvt_tf32(V2[k * 32 + n]));
    }
}

// ---------------- main kernel ----------------
__global__ __launch_bounds__(TPB, 1)
void ffn_mma(const float* __restrict__ x,
             const float* __restrict__ nw0, const float* __restrict__ nb0,
             const float* __restrict__ nw1, const float* __restrict__ nw2,
             const float* __restrict__ b0,  const float* __restrict__ c0,
             const float* __restrict__ alpha,
             float* __restrict__ out) {
    extern __shared__ float SM[];
    const int tid = threadIdx.x, wid = tid >> 5, lane = tid & 31;
    const int ms = wid & 3, ns = wid >> 2;
    const int g = lane >> 2, t4 = lane & 3;
    const int row0 = blockIdx.x * MR;
    const float ta = tanhf(alpha[0]);

    // ===== norms: 16 warps x 4 rows -> Y0F (tf32 frag) + invA =====
    #pragma unroll
    for (int rr = 0; rr < 4; ++rr) {
        const int r = wid * 4 + rr;
        const float* xr = x + (size_t)(row0 + r) * 480;
        float vals[15], sum0 = 0.f, sq0 = 0.f, sq12 = 0.f;
        #pragma unroll
        for (int k = 0; k < 15; ++k) {
            const float v = xr[lane + 32 * k];
            vals[k] = v;
            if (k < 4)       { sum0 += v; sq0 += v * v; }
            else if (k < 10) { sq12 += v * v * (0.5f / 192.0f); }
            else             { sq12 += v * v * (0.5f / 160.0f); }
        }
        #pragma unroll
        for (int o = 16; o > 0; o >>= 1) {
            sum0 += __shfl_xor_sync(0xffffffffu, sum0, o);
            sq0  += __shfl_xor_sync(0xffffffffu, sq0,  o);
            sq12 += __shfl_xor_sync(0xffffffffu, sq12, o);
        }
        const float mu  = sum0 * (1.0f / 128.0f);
        const float var = sq0 * (1.0f / 128.0f) - mu * mu;
        const float is0 = rsqrtf(var + EPSF);
        const float iv  = rsqrtf(sq12 + EPSF);
        if (lane == 0) SM[INVA + r] = iv;
        const int rms = r >> 4, rg = r & 7, rhi = (r >> 3) & 1;
        #pragma unroll
        for (int k = 0; k < 4; ++k) {
            const int c = lane + 32 * k;
            const float y = ((vals[k] - mu) * is0 * nw0[c] + nb0[c]) * INV_S0;
            const int kb = c >> 3, ct = c & 3, khi = (c >> 2) & 1;
            SM[Y0F + (kb * 4 + rms) * 128 + (rg * 4 + ct) * 4 + rhi + 2 * khi] =
                __uint_as_float(cvt_tf32(y));
        }
    }
    __syncthreads();

    // ===== Phase A: 8 chunks: h0 -> silu -> s -> o0 accumulate =====
    float o0a[4][4];
    #pragma unroll
    for (int t = 0; t < 4; ++t)
        #pragma unroll
        for (int e = 0; e < 4; ++e) o0a[t][e] = 0.f;

    for (int nc = 0; nc < 8; ++nc) {
        copy4(SM, STGB, W0F_g + nc * 8192, 8192);
        __syncthreads();
        float h[2][4];
        #pragma unroll
        for (int t = 0; t < 2; ++t)
            #pragma unroll
            for (int e = 0; e < 4; ++e) h[t][e] = 0.f;
        gemm_n64(SM, Y0F, STGB, 16, ms, ns, lane, h);
        #pragma unroll
        for (int t = 0; t < 2; ++t) {
            const int cb = 16 * ns + 8 * t + 2 * t4;         // n64 column mapping
            const int col = 64 * nc + cb;
            const float bb0 = b0[col], bb1 = b0[col + 1];
            const int r0 = 16 * ms + g;
            float v0 = h[t][0] + bb0, v1 = h[t][1] + bb1;
            float v2 = h[t][2] + bb0, v3 = h[t][3] + bb1;
            float2 z0, z1;
            z0.x = v0 * __fdividef(1.f, 1.f + __expf(-v0)) * INV_T0;
            z0.y = v1 * __fdividef(1.f, 1.f + __expf(-v1)) * INV_T0;
            z1.x = v2 * __fdividef(1.f, 1.f + __expf(-v2)) * INV_T0;
            z1.y = v3 * __fdividef(1.f, 1.f + __expf(-v3)) * INV_T0;
            *(float2*)(SM + LB1 + r0 * 68 + cb)       = z0;
            *(float2*)(SM + LB1 + (r0 + 8) * 68 + cb) = z1;
        }
        __syncthreads();
        refrag(SM, AFB, LB1);
        copy4(SM, STGB, V0F_g + nc * 8192, 8192);
        __syncthreads();
        gemm_n128(SM, AFB, STGB, 8, ms, ns, lane, o0a);
        __syncthreads();
    }
    // o0 -> out (cols 0..128); gemm_n128 column mapping (32*ns)
    #pragma unroll
    for (int t = 0; t < 4; ++t) {
        const int cb = 32 * ns + 8 * t + 2 * t4;
        const float cc0 = c0[cb], cc1 = c0[cb + 1];
        const size_t i0 = (size_t)(row0 + 16 * ms + g) * 480 + cb;
        const size_t i1 = i0 + (size_t)8 * 480;
        float2 xv0 = *(const float2*)(x + i0), xv1 = *(const float2*)(x + i1);
        float2 ov0, ov1;
        ov0.x = xv0.x + ta * (o0a[t][0] + cc0); ov0.y = xv0.y + ta * (o0a[t][1] + cc1);
        ov1.x = xv1.x + ta * (o0a[t][2] + cc0); ov1.y = xv1.y + ta * (o0a[t][3] + cc1);
        *(float2*)(out + i0) = ov0;
        *(float2*)(out + i1) = ov1;
    }

    // ===== Phase B: build y1F; 4 chunks x (gate + 3 heads) =====
    for (int i = tid; i < 3 * 4096; i += TPB) {
        const int m = i >> 12, w = i & 4095;
        int r, k; frag_src(w, r, k);
        const float v = x[(size_t)(row0 + r) * 480 + 128 + 3 * k + m]
                        * SM[INVA + r] * nw1[k] * INV_S1;
        SM[YMF + i] = __uint_as_float(cvt_tf32(v));
    }
    __syncthreads();

    float o1a[3][2][4];
    #pragma unroll
    for (int m = 0; m < 3; ++m)
        #pragma unroll
        for (int t = 0; t < 2; ++t)
            #pragma unroll
            for (int e = 0; e < 4; ++e) o1a[m][t][e] = 0.f;

    for (int c = 0; c < 4; ++c) {
        copy4(SM, STGB, W0F_g + (8 + c) * 8192, 8192);
        __syncthreads();
        float gf[2][4];
        #pragma unroll
        for (int t = 0; t < 2; ++t)
            #pragma unroll
            for (int e = 0; e < 4; ++e) gf[t][e] = 0.f;
        gemm_n64(SM, Y0F, STGB, 16, ms, ns, lane, gf);
        #pragma unroll
        for (int t = 0; t < 2; ++t) {
            const int cb = 16 * ns + 8 * t + 2 * t4;         // n64 column mapping
            const int col = 512 + 64 * c + cb;
            const float bb0 = b0[col], bb1 = b0[col + 1];
            const int r0 = 16 * ms + g;
            float2 s0, s1;
            s0.x = __fdividef(1.f, 1.f + __expf(-(gf[t][0] + bb0)));
            s0.y = __fdividef(1.f, 1.f + __expf(-(gf[t][1] + bb1)));
            s1.x = __fdividef(1.f, 1.f + __expf(-(gf[t][2] + bb0)));
            s1.y = __fdividef(1.f, 1.f + __expf(-(gf[t][3] + bb1)));
            *(float2*)(SM + LB0 + r0 * 68 + cb)       = s0;
            *(float2*)(SM + LB0 + (r0 + 8) * 68 + cb) = s1;
        }
        __syncthreads();
        copy4(SM, STGB, W1F_g + c * 4096, 4096);
        copy4(SM, STGB + 4096, V1F_g + c * 4096, 4096);
        __syncthreads();
        for (int m = 0; m < 3; ++m) {
            float h[2][4];
            #pragma unroll
            for (int t = 0; t < 2; ++t)
                #pragma unroll
                for (int e = 0; e < 4; ++e) h[t][e] = 0.f;
            gemm_n64(SM, YMF + m * 4096, STGB, 8, ms, ns, lane, h);
            #pragma unroll
            for (int t = 0; t < 2; ++t) {
                const int cb = 16 * ns + 8 * t + 2 * t4;     // n64 column mapping
                const int r0 = 16 * ms + g;
                const float2 g0 = *(const float2*)(SM + LB0 + r0 * 68 + cb);
                const float2 g1 = *(const float2*)(SM + LB0 + (r0 + 8) * 68 + cb);
                float2 z0, z1;
                z0.x = h[t][0] * g0.x * INV_T1; z0.y = h[t][1] * g0.y * INV_T1;
                z1.x = h[t][2] * g1.x * INV_T1; z1.y = h[t][3] * g1.y * INV_T1;
                *(float2*)(SM + LB1 + r0 * 68 + cb)       = z0;
                *(float2*)(SM + LB1 + (r0 + 8) * 68 + cb) = z1;
            }
            __syncthreads();
            refrag(SM, AFB, LB1);
            __syncthreads();
            gemm_n64(SM, AFB, STGB + 4096, 8, ms, ns, lane, o1a[m]);
            __syncthreads();
        }
    }
    // o1 -> stage (stride 196) -> out cols 128..320 (n64 mapping: 16*ns)
    {
        float* S = SM + YMF;
        #pragma unroll
        for (int m = 0; m < 3; ++m)
            #pragma unroll
            for (int t = 0; t < 2; ++t) {
                const int w0 = 16 * ns + 8 * t + 2 * t4;
                const int r0 = 16 * ms + g, r1 = r0 + 8;
                S[r0 * 196 + 3 * w0 + m]       = o1a[m][t][0];
                S[r0 * 196 + 3 * (w0 + 1) + m] = o1a[m][t][1];
                S[r1 * 196 + 3 * w0 + m]       = o1a[m][t][2];
                S[r1 * 196 + 3 * (w0 + 1) + m] = o1a[m][t][3];
            }
        __syncthreads();
        for (int i = tid; i < 64 * 192; i += TPB) {
            const int r = i / 192, j = i - r * 192;
            const size_t idx = (size_t)(row0 + r) * 480 + 128 + j;
            out[idx] = x[idx] + ta * S[r * 196 + j];
        }
        __syncthreads();
    }

    // ===== Phase C: build y2F; 2 chunks x (gate + 5 heads) =====
    for (int i = tid; i < 5 * 2048; i += TPB) {
        const int m = i >> 11, w = i & 2047;
        int r, k; frag_src(w, r, k);
        const float v = x[(size_t)(row0 + r) * 480 + 320 + 5 * k + m]
                        * SM[INVA + r] * nw2[k] * INV_S2;
        SM[YMF + i] = __uint_as_float(cvt_tf32(v));
    }
    __syncthreads();

    float o2a[5][4];
    #pragma unroll
    for (int m = 0; m < 5; ++m)
        #pragma unroll
        for (int e = 0; e < 4; ++e) o2a[m][e] = 0.f;

    for (int c = 0; c < 2; ++c) {
        copy4(SM, STGB, W0F_g + (12 + c) * 8192, 8192);
        __syncthreads();
        float gf[2][4];
        #pragma unroll
        for (int t = 0; t < 2; ++t)
            #pragma unroll
            for (int e = 0; e < 4; ++e) gf[t][e] = 0.f;
        gemm_n64(SM, Y0F, STGB, 16, ms, ns, lane, gf);
        #pragma unroll
        for (int t = 0; t < 2; ++t) {
            const int cb = 16 * ns + 8 * t + 2 * t4;         // n64 column mapping
            const int col = 768 + 64 * c + cb;
            const float bb0 = b0[col], bb1 = b0[col + 1];
            const int r0 = 16 * ms + g;
            float2 s0, s1;
            s0.x = __fdividef(1.f, 1.f + __expf(-(gf[t][0] + bb0)));
            s0.y = __fdividef(1.f, 1.f + __expf(-(gf[t][1] + bb1)));
            s1.x = __fdividef(1.f, 1.f + __expf(-(gf[t][2] + bb0)));
            s1.y = __fdividef(1.f, 1.f + __expf(-(gf[t][3] + bb1)));
            *(float2*)(SM + LB0 + r0 * 68 + cb)       = s0;
            *(float2*)(SM + LB0 + (r0 + 8) * 68 + cb) = s1;
        }
        __syncthreads();
        copy4(SM, STGB, W2F_g + c * 2048, 2048);
        copy4(SM, STGB + 2048, V2F_g + c * 2048, 2048);
        __syncthreads();
        for (int m = 0; m < 5; ++m) {
            float h[2][4];
            #pragma unroll
            for (int t = 0; t < 2; ++t)
                #pragma unroll
                for (int e = 0; e < 4; ++e) h[t][e] = 0.f;
            gemm_n64(SM, YMF + m * 2048, STGB, 4, ms, ns, lane, h);
            #pragma unroll
            for (int t = 0; t < 2; ++t) {
                const int cb = 16 * ns + 8 * t + 2 * t4;     // n64 column mapping
                const int r0 = 16 * ms + g;
                const float2 g0 = *(const float2*)(SM + LB0 + r0 * 68 + cb);
                const float2 g1 = *(const float2*)(SM + LB0 + (r0 + 8) * 68 + cb);
                float2 z0, z1;
                z0.x = h[t][0] * g0.x * INV_T2; z0.y = h[t][1] * g0.y * INV_T2;
                z1.x = h[t][2] * g1.x * INV_T2; z1.y = h[t][3] * g1.y * INV_T2;
                *(float2*)(SM + LB1 + r0 * 68 + cb)       = z0;
                *(float2*)(SM + LB1 + (r0 + 8) * 68 + cb) = z1;
            }
            __syncthreads();
            refrag(SM, AFB, LB1);
            __syncthreads();
            gemm_n32(SM, AFB, STGB + 2048, 8, ms, ns, lane, o2a[m]);
            __syncthreads();
        }
    }
    // o2 -> stage (stride 164) -> out cols 320..480 (n32 mapping: 8*ns)
    {
        float* S = SM + YMF;
        #pragma unroll
        for (int m = 0; m < 5; ++m) {
            const int w0 = 8 * ns + 2 * t4;
            const int r0 = 16 * ms + g, r1 = r0 + 8;
            S[r0 * 164 + 5 * w0 + m]       = o2a[m][0];
            S[r0 * 164 + 5 * (w0 + 1) + m] = o2a[m][1];
            S[r1 * 164 + 5 * w0 + m]       = o2a[m][2];
            S[r1 * 164 + 5 * (w0 + 1) + m] = o2a[m][3];
        }
        __syncthreads();
        for (int i = tid; i < 64 * 160; i += TPB) {
            const int r = i / 160, j = i - r * 160;
            const size_t idx = (size_t)(row0 + r) * 480 + 320 + j;
            out[idx] = x[idx] + ta * S[r * 164 + j];
        }
    }
}

extern "C" void kernel_launch(void* const* d_in, const int* in_sizes, int n_in,
                              void* d_out, int out_size) {
    const float* x     = (const float*)d_in[0];
    const float* nw0   = (const float*)d_in[1];
    const float* nb0   = (const float*)d_in[2];
    const float* nw1   = (const float*)d_in[3];
    const float* nw2   = (const float*)d_in[4];
    const float* W0    = (const float*)d_in[5];
    const float* b0    = (const float*)d_in[6];
    const float* W1    = (const float*)d_in[7];
    const float* W2    = (const float*)d_in[8];
    const float* V0    = (const float*)d_in[9];
    const float* c0    = (const float*)d_in[10];
    const float* V1    = (const float*)d_in[11];
    const float* V2    = (const float*)d_in[12];
    const float* alpha = (const float*)d_in[13];
    float* out = (float*)d_out;

    prep_kernel<<<240, 256>>>(W0, W1, W2, V0, V1, V2);
    cudaFuncSetAttribute(ffn_mma, cudaFuncAttributeMaxDynamicSharedMemorySize,
                         SMW * 4);
    const int grid = (in_sizes[0] / 480) / MR;
    ffn_mma<<<grid, TPB, SMW * 4>>>(x, nw0, nb0, nw1, nw2, b0, c0, alpha, out);
}